// round 1
// baseline (speedup 1.0000x reference)
#include <cuda_runtime.h>

// PerLeadTimeLSTM: B=131072, LEADS=42, INPUT_DIM=2, HIDDEN=10.
// Single-step LSTM with zero init state: f-gate is dead (f*c0 == 0).
// y[b,t,:] = W_fc[t] @ (sigmoid(o)*tanh(sigmoid(i)*tanh(g))) + b_fc[t]
// where [i|g|o] gates = W_ih[t] @ x[b,t,:] + (b_ih+b_hh)[t].
//
// Strategy: thread handles NB=8 batch elems of ONE lead (stride 42*16384 elems
// keeps lead constant AND keeps x/y float2 accesses fully coalesced).
// Weights preloaded to smem, i/o rows pre-scaled by 0.5 so
// sigmoid(z) = fma(0.5, tanh(z_half), 0.5) = 1 MUFU.TANH + 1 FMA.

#define B_TOT   131072
#define T_LEADS 42
#define HID     10
#define NB      8
#define NTH_TOTAL (B_TOT * T_LEADS / NB)   // 688128 threads, exact
#define BLOCK   256
#define PS      113   // padded smem stride (floats) per lead; odd -> spread banks

__device__ __forceinline__ float tanh_apx(float x) {
    float r;
    asm("tanh.approx.f32 %0, %1;" : "=f"(r) : "f"(x));
    return r;
}

__global__ __launch_bounds__(BLOCK)
void perlead_lstm_kernel(
    const float* __restrict__ x,      // (B, 42, 2)
    const float* __restrict__ W_ih,   // (42, 40, 2)
    const float* __restrict__ b_ih,   // (42, 40)
    const float* __restrict__ b_hh,   // (42, 40)
    const float* __restrict__ W_fc,   // (42, 2, 10)
    const float* __restrict__ b_fc,   // (42, 2)
    float* __restrict__ y_out)        // (B, 42, 2)
{
    __shared__ float w[T_LEADS * PS];

    // ---- Preload + fold weights into smem ----
    // Per-lead layout (offsets in floats):
    //  [0..19]   w_i (j-major pairs), pre-scaled 0.5
    //  [20..39]  w_g
    //  [40..59]  w_o, pre-scaled 0.5
    //  [60..69]  bias_i = 0.5*(b_ih+b_hh)[0..9]
    //  [70..79]  bias_g =      (b_ih+b_hh)[20..29]
    //  [80..89]  bias_o = 0.5*(b_ih+b_hh)[30..39]
    //  [90..109] w_fc pairs (d0_j, d1_j)
    //  [110..111] b_fc
    for (int idx = threadIdx.x; idx < T_LEADS * 112; idx += BLOCK) {
        int t = idx / 112;
        int off = idx % 112;
        float v;
        if (off < 20) {
            int j = off >> 1, d = off & 1;
            v = 0.5f * W_ih[t*80 + j*2 + d];                 // i-gate rows 0..9
        } else if (off < 40) {
            int o2 = off - 20; int j = o2 >> 1, d = o2 & 1;
            v = W_ih[t*80 + (20 + j)*2 + d];                 // g-gate rows 20..29
        } else if (off < 60) {
            int o2 = off - 40; int j = o2 >> 1, d = o2 & 1;
            v = 0.5f * W_ih[t*80 + (30 + j)*2 + d];          // o-gate rows 30..39
        } else if (off < 70) {
            int j = off - 60;
            v = 0.5f * (b_ih[t*40 + j] + b_hh[t*40 + j]);
        } else if (off < 80) {
            int j = off - 70;
            v = b_ih[t*40 + 20 + j] + b_hh[t*40 + 20 + j];
        } else if (off < 90) {
            int j = off - 80;
            v = 0.5f * (b_ih[t*40 + 30 + j] + b_hh[t*40 + 30 + j]);
        } else if (off < 110) {
            int o2 = off - 90; int j = o2 >> 1, d = o2 & 1;
            v = W_fc[t*20 + d*10 + j];
        } else {
            int d = off - 110;
            v = b_fc[t*2 + d];
        }
        w[t * PS + off] = v;
    }
    __syncthreads();

    int g = blockIdx.x * BLOCK + threadIdx.x;        // 0 .. 688127
    int t = g % T_LEADS;                             // same lead for all NB elems
    const float* wt = &w[t * PS];

    float x0[NB], x1[NB], y0[NB], y1[NB];
    const float2* x2 = (const float2*)x;
    float bf0 = wt[110], bf1 = wt[111];

    #pragma unroll
    for (int k = 0; k < NB; k++) {
        float2 xv = x2[g + k * NTH_TOTAL];
        x0[k] = xv.x; x1[k] = xv.y;
        y0[k] = bf0;  y1[k] = bf1;
    }

    #pragma unroll
    for (int j = 0; j < HID; j++) {
        float wi0 = wt[2*j],      wi1 = wt[2*j + 1];
        float wg0 = wt[20 + 2*j], wg1 = wt[21 + 2*j];
        float wo0 = wt[40 + 2*j], wo1 = wt[41 + 2*j];
        float bi  = wt[60 + j],   bg  = wt[70 + j],  bo = wt[80 + j];
        float f0  = wt[90 + 2*j], f1  = wt[91 + 2*j];
        #pragma unroll
        for (int k = 0; k < NB; k++) {
            float zi = fmaf(wi1, x1[k], fmaf(wi0, x0[k], bi));  // already /2
            float zg = fmaf(wg1, x1[k], fmaf(wg0, x0[k], bg));
            float zo = fmaf(wo1, x1[k], fmaf(wo0, x0[k], bo));  // already /2
            float si = fmaf(0.5f, tanh_apx(zi), 0.5f);          // sigmoid(i)
            float tg = tanh_apx(zg);
            float c  = si * tg;
            float tc = tanh_apx(c);
            float so = fmaf(0.5f, tanh_apx(zo), 0.5f);          // sigmoid(o)
            float h  = so * tc;
            y0[k] = fmaf(f0, h, y0[k]);
            y1[k] = fmaf(f1, h, y1[k]);
        }
    }

    float2* yo = (float2*)y_out;
    #pragma unroll
    for (int k = 0; k < NB; k++) {
        yo[g + k * NTH_TOTAL] = make_float2(y0[k], y1[k]);
    }
}

extern "C" void kernel_launch(void* const* d_in, const int* in_sizes, int n_in,
                              void* d_out, int out_size) {
    perlead_lstm_kernel<<<NTH_TOTAL / BLOCK, BLOCK>>>(
        (const float*)d_in[0],   // x
        (const float*)d_in[1],   // W_ih
        (const float*)d_in[2],   // b_ih
        (const float*)d_in[3],   // b_hh
        (const float*)d_in[4],   // W_fc
        (const float*)d_in[5],   // b_fc
        (float*)d_out);
}